// round 14
// baseline (speedup 1.0000x reference)
#include <cuda_runtime.h>
#include <cuda_bf16.h>
#include <cstdint>
#include <math.h>

#define BDIM 16
#define GDIM 2048
#define DDIM 256
#define NHEADS 8
#define HEADDIM 32
#define FFND 1024
#define LAYERS 4
#define ROWS (BDIM*GDIM)   // 32768
#define CHUNK 64
#define NCHUNK (GDIM/CHUNK)      // 32
#define BH (BDIM*NHEADS)         // 128
#define STATE_STRIDE 1056        // 32*32 + 32

// ---------------------------------------------------------------------------
// Scratch (device globals; no runtime allocation allowed)
// ---------------------------------------------------------------------------
__device__ float g_h [ROWS*DDIM];
__device__ float g_q [ROWS*DDIM];
__device__ float g_k [ROWS*DDIM];
__device__ float g_v [ROWS*DDIM];
__device__ float g_state[(size_t)BH*NCHUNK*STATE_STRIDE];

__device__ __nv_bfloat16 g_hnhi[ROWS*DDIM],  g_hnlo[ROWS*DDIM];
__device__ __nv_bfloat16 g_midhi[(size_t)ROWS*FFND], g_midlo[(size_t)ROWS*FFND];
// Transposed split weights ([N,K] layout). QKV concatenated: rows 0..255=Q, 256..511=K, 512..767=V
__device__ __nv_bfloat16 g_wqkvh[LAYERS*768*DDIM], g_wqkvl[LAYERS*768*DDIM];
__device__ __nv_bfloat16 g_wuh[LAYERS*DDIM*FFND],  g_wul[LAYERS*DDIM*FFND];
__device__ __nv_bfloat16 g_wvh2[LAYERS*FFND*DDIM], g_wvl2[LAYERS*FFND*DDIM];

// ---------------------------------------------------------------------------
// Warp-level MMA helpers (base sm_103-legal PTX)
// ---------------------------------------------------------------------------
__device__ __forceinline__ uint32_t smem_to_u32(const void* p) {
    uint32_t a;
    asm("{ .reg .u64 t; cvta.to.shared.u64 t, %1; cvt.u32.u64 %0, t; }" : "=r"(a) : "l"(p));
    return a;
}
__device__ __forceinline__ void ldsm4(uint32_t* r, uint32_t addr) {
    asm volatile("ldmatrix.sync.aligned.m8n8.x4.shared.b16 {%0,%1,%2,%3}, [%4];"
        : "=r"(r[0]), "=r"(r[1]), "=r"(r[2]), "=r"(r[3]) : "r"(addr));
}
__device__ __forceinline__ void mma16816(float* c, const uint32_t* a, const uint32_t* b) {
    asm volatile(
        "mma.sync.aligned.m16n8k16.row.col.f32.bf16.bf16.f32 "
        "{%0,%1,%2,%3}, {%4,%5,%6,%7}, {%8,%9}, {%0,%1,%2,%3};"
        : "+f"(c[0]), "+f"(c[1]), "+f"(c[2]), "+f"(c[3])
        : "r"(a[0]), "r"(a[1]), "r"(a[2]), "r"(a[3]), "r"(b[0]), "r"(b[1]));
}
__device__ __forceinline__ void cpasync16(uint32_t dst, const void* src) {
    asm volatile("cp.async.cg.shared.global [%0], [%1], 16;" :: "r"(dst), "l"(src));
}
#define CP_COMMIT() asm volatile("cp.async.commit_group;" ::: "memory")
#define CP_WAIT(n)  asm volatile("cp.async.wait_group %0;" :: "n"(n) : "memory")

// ---------------------------------------------------------------------------
// Embedding
// ---------------------------------------------------------------------------
__global__ void embed_kernel(const float* __restrict__ x,
                             const float* __restrict__ gene_emb,
                             const float* __restrict__ inv_freq,
                             float* __restrict__ h) {
    int row = blockIdx.x;
    int g   = row % GDIM;
    int i   = threadIdx.x;
    float xv = x[row];
    float fr = xv * inv_freq[i];
    float s, c;
    sincosf(fr, &s, &c);
    if (xv == -10.0f) { s = 0.0f; c = 0.0f; }
    h[row*DDIM + i]       = gene_emb[g*DDIM + i]       + s;
    h[row*DDIM + 128 + i] = gene_emb[g*DDIM + 128 + i] + c;
}

// ---------------------------------------------------------------------------
// LayerNorm -> split bf16 (hi/lo)
// ---------------------------------------------------------------------------
__global__ void ln_bf16_kernel(const float* __restrict__ in,
                               const float* __restrict__ gamma,
                               const float* __restrict__ beta,
                               __nv_bfloat16* __restrict__ ohi,
                               __nv_bfloat16* __restrict__ olo) {
    int row = blockIdx.x;
    int i = threadIdx.x;
    float v = in[row*DDIM + i];
    float s1 = v, s2 = v*v;
    #pragma unroll
    for (int o = 16; o; o >>= 1) {
        s1 += __shfl_xor_sync(0xffffffffu, s1, o);
        s2 += __shfl_xor_sync(0xffffffffu, s2, o);
    }
    __shared__ float r1[8], r2[8];
    if ((i & 31) == 0) { r1[i>>5] = s1; r2[i>>5] = s2; }
    __syncthreads();
    float t1 = 0.f, t2 = 0.f;
    #pragma unroll
    for (int w = 0; w < 8; w++) { t1 += r1[w]; t2 += r2[w]; }
    float m   = t1 * (1.0f/256.0f);
    float var = t2 * (1.0f/256.0f) - m*m;
    float inv = rsqrtf(var + 1e-5f);
    float y = (v - m) * inv * gamma[i] + beta[i];
    __nv_bfloat16 hi = __float2bfloat16(y);
    __nv_bfloat16 lo = __float2bfloat16(y - __bfloat162float(hi));
    ohi[(size_t)row*DDIM + i] = hi;
    olo[(size_t)row*DDIM + i] = lo;
}

// ---------------------------------------------------------------------------
// Weight transpose + split, batched over layers (blockIdx.z = layer).
// W[K,N] fp32 -> out[(rowOff+n), k] bf16 hi/lo, output row-dim = ldRows.
// ---------------------------------------------------------------------------
__global__ void wconv_kernel(const float* __restrict__ W,
                             __nv_bfloat16* __restrict__ hi,
                             __nv_bfloat16* __restrict__ lo,
                             int K, int N, int rowOff, int ldRows) {
    __shared__ float t[32][33];
    int l = blockIdx.z;
    const float* Wl = W + (size_t)l * K * N;
    size_t obase = (size_t)l * ldRows * K;
    int nb = blockIdx.x*32, kb = blockIdx.y*32;
    int tx = threadIdx.x & 31, ty = threadIdx.x >> 5;
    #pragma unroll
    for (int j = 0; j < 32; j += 8)
        t[ty+j][tx] = Wl[(size_t)(kb+ty+j)*N + nb+tx];
    __syncthreads();
    #pragma unroll
    for (int j = 0; j < 32; j += 8) {
        float v = t[tx][ty+j];
        __nv_bfloat16 h = __float2bfloat16(v);
        __nv_bfloat16 l2 = __float2bfloat16(v - __bfloat162float(h));
        size_t o = obase + (size_t)(rowOff + nb+ty+j)*K + kb+tx;
        hi[o] = h; lo[o] = l2;
    }
}

// ---------------------------------------------------------------------------
// Pipelined warp-MMA split-bf16 GEMM, BM=128 BN=128 BK=64, 2-stage cp.async.
// 8 warps (2 in M x 4 in N), warp tile 64x32. B loaded via ldsm4.
// EPI: 0 none(fp32), 1 qkv (3 outputs, square for first two), 2 gelu->bf16 hi/lo,
//      3 residual add(fp32)
// Nout = row stride of each output buffer. For EPI=1 B has 768 rows, outputs 256 each.
// ---------------------------------------------------------------------------
#define ASTR 72
#define S_AHI 0
#define S_ALO 18432
#define S_BHI 36864
#define S_BLO 55296
#define S_SS  73728
#define S_SMEM (2*S_SS)   // 147456

template<int EPI>
__global__ __launch_bounds__(256, 1) void tc_gemm2(
    const __nv_bfloat16* __restrict__ Ahi, const __nv_bfloat16* __restrict__ Alo,
    const __nv_bfloat16* __restrict__ Bhi, const __nv_bfloat16* __restrict__ Blo,
    const float* __restrict__ b0, const float* __restrict__ b1, const float* __restrict__ b2,
    const float* __restrict__ resid,
    float* __restrict__ o0, float* __restrict__ o1, float* __restrict__ o2,
    __nv_bfloat16* __restrict__ Chi, __nv_bfloat16* __restrict__ Clo,
    int Nout, int K)
{
    extern __shared__ char smem[];
    uint32_t sbase = smem_to_u32(smem);

    int tid  = threadIdx.x;
    int lane = tid & 31;
    int warp = tid >> 5;
    int wm = warp >> 2;       // 0..1
    int wn = warp & 3;        // 0..3
    int bm = blockIdx.x * 128, bn = blockIdx.y * 128;

    float acc[4][4][4];
    #pragma unroll
    for (int mi = 0; mi < 4; mi++)
        #pragma unroll
        for (int ni = 0; ni < 4; ni++)
            #pragma unroll
            for (int e = 0; e < 4; e++) acc[mi][ni][e] = 0.f;

    const int nkt = K >> 6;

    auto issue = [&](int st, int kt) {
        uint32_t sb = sbase + st * S_SS;
        #pragma unroll
        for (int i = tid; i < 1024; i += 256) {
            int r = i >> 3, kc = (i & 7) * 8;
            uint32_t d = sb + (uint32_t)((r*ASTR + kc) * 2);
            size_t ga = (size_t)(bm + r) * K + kt + kc;
            cpasync16(d + S_AHI, Ahi + ga);
            cpasync16(d + S_ALO, Alo + ga);
            size_t gb = (size_t)(bn + r) * K + kt + kc;
            cpasync16(d + S_BHI, Bhi + gb);
            cpasync16(d + S_BLO, Blo + gb);
        }
    };

    issue(0, 0);
    CP_COMMIT();

    int lr = lane & 15, lc = (lane >> 4) * 8;

    for (int it = 0; it < nkt; it++) {
        if (it + 1 < nkt) { issue((it+1) & 1, (it+1) << 6); CP_COMMIT(); CP_WAIT(1); }
        else              { CP_WAIT(0); }
        __syncthreads();
        uint32_t sb = sbase + (it & 1) * S_SS;
        #pragma unroll
        for (int ks = 0; ks < 4; ks++) {
            uint32_t ah[4][4], al[4][4], bh[2][4], bl[2][4];
            #pragma unroll
            for (int mi = 0; mi < 4; mi++) {
                uint32_t ad = sb + (uint32_t)(((wm*64 + mi*16 + lr)*ASTR + ks*16 + lc) * 2);
                ldsm4(ah[mi], ad + S_AHI);
                ldsm4(al[mi], ad + S_ALO);
            }
            #pragma unroll
            for (int nh = 0; nh < 2; nh++) {
                uint32_t bd = sb + (uint32_t)(((wn*32 + nh*16 + lr)*ASTR + ks*16 + lc) * 2);
                ldsm4(bh[nh], bd + S_BHI);
                ldsm4(bl[nh], bd + S_BLO);
            }
            #pragma unroll
            for (int mi = 0; mi < 4; mi++)
                #pragma unroll
                for (int ni = 0; ni < 4; ni++) {
                    int nh = ni >> 1, sub = ni & 1;
                    uint32_t bfh[2] = {bh[nh][sub], bh[nh][sub+2]};
                    uint32_t bfl[2] = {bl[nh][sub], bl[nh][sub+2]};
                    mma16816(acc[mi][ni], ah[mi], bfh);
                    mma16816(acc[mi][ni], ah[mi], bfl);
                    mma16816(acc[mi][ni], al[mi], bfh);
                }
        }
        __syncthreads();
    }

    // ---- epilogue
    int r0 = lane >> 2, c0 = (lane & 3) * 2;
    #pragma unroll
    for (int mi = 0; mi < 4; mi++) {
        #pragma unroll
        for (int ni = 0; ni < 4; ni++) {
            int colg = bn + wn*32 + ni*8 + c0;
            if (EPI == 1) {
                int m = colg >> 8;
                int coll = colg & 255;
                const float* bp = (m == 0) ? b0 : (m == 1) ? b1 : b2;
                float* op = (m == 0) ? o0 : (m == 1) ? o1 : o2;
                float bb0 = __ldg(&bp[coll]), bb1 = __ldg(&bp[coll+1]);
                #pragma unroll
                for (int hrow = 0; hrow < 2; hrow++) {
                    int row = bm + wm*64 + mi*16 + r0 + hrow*8;
                    float v0 = acc[mi][ni][hrow*2+0] + bb0;
                    float v1 = acc[mi][ni][hrow*2+1] + bb1;
                    if (m < 2) { v0 = v0*v0; v1 = v1*v1; }
                    float2 ov = {v0, v1};
                    *(float2*)&op[(size_t)row * Nout + coll] = ov;
                }
            } else {
                float bb0 = __ldg(&b0[colg]), bb1 = __ldg(&b0[colg+1]);
                #pragma unroll
                for (int hrow = 0; hrow < 2; hrow++) {
                    int row = bm + wm*64 + mi*16 + r0 + hrow*8;
                    float v0 = acc[mi][ni][hrow*2+0] + bb0;
                    float v1 = acc[mi][ni][hrow*2+1] + bb1;
                    size_t o = (size_t)row * Nout + colg;
                    if (EPI == 2) {
                        float gg0 = 0.5f * v0 * (1.0f + erff(v0 * 0.70710678118654752f));
                        float gg1 = 0.5f * v1 * (1.0f + erff(v1 * 0.70710678118654752f));
                        __nv_bfloat16 h0 = __float2bfloat16(gg0);
                        __nv_bfloat16 h1 = __float2bfloat16(gg1);
                        __nv_bfloat162 hv; hv.x = h0; hv.y = h1;
                        __nv_bfloat162 lv;
                        lv.x = __float2bfloat16(gg0 - __bfloat162float(h0));
                        lv.y = __float2bfloat16(gg1 - __bfloat162float(h1));
                        *(__nv_bfloat162*)&Chi[o] = hv;
                        *(__nv_bfloat162*)&Clo[o] = lv;
                    } else if (EPI == 3) {
                        float2 rs = *(const float2*)&resid[o];
                        float2 ov = {v0 + rs.x, v1 + rs.y};
                        *(float2*)&o0[o] = ov;
                    } else {
                        float2 ov = {v0, v1};
                        *(float2*)&o0[o] = ov;
                    }
                }
            }
        }
    }
}

// ---------------------------------------------------------------------------
// Chunked causal linear attention (unchanged)
// ---------------------------------------------------------------------------
__global__ void attn_state_kernel(const float* __restrict__ K,
                                  const float* __restrict__ V,
                                  float* __restrict__ state) {
    int blk = blockIdx.x;
    int bh  = blk >> 5;
    int c   = blk & 31;
    int b = bh >> 3, hh = bh & 7;
    int f = threadIdx.x & 31;
    int d = threadIdx.x >> 5;
    size_t base = ((size_t)(b*GDIM + c*CHUNK))*DDIM + hh*HEADDIM;
    float s = 0.f, ks = 0.f;
    #pragma unroll 4
    for (int t = 0; t < CHUNK; t++) {
        float kf = K[base + f];
        float vd = V[base + d];
        s  = fmaf(kf, vd, s);
        ks += kf;
        base += DDIM;
    }
    float* st = state + (size_t)blk * STATE_STRIDE;
    st[d*32 + f] = s;
    if (d == 0) st[1024 + f] = ks;
}

__global__ void attn_prefix_kernel(float* __restrict__ state) {
    int bh = blockIdx.x;
    float* st = state + (size_t)bh * NCHUNK * STATE_STRIDE;
    for (int e = threadIdx.x; e < STATE_STRIDE; e += blockDim.x) {
        float run = 0.f;
        float* p = st + e;
        #pragma unroll 4
        for (int c = 0; c < NCHUNK; c++) {
            float t = *p;
            *p = run;
            run += t;
            p += STATE_STRIDE;
        }
    }
}

__global__ __launch_bounds__(256) void attn_out_kernel(
        const float* __restrict__ Q,
        const float* __restrict__ K,
        const float* __restrict__ V,
        const float* __restrict__ state,
        float* __restrict__ H) {
    int blk = blockIdx.x;
    int bh  = blk >> 5;
    int c   = blk & 31;
    int b = bh >> 3, hh = bh & 7;

    __shared__ float Qs[CHUNK*33];
    __shared__ float Ks[CHUNK*33];
    __shared__ float Vs[CHUNK*33];
    __shared__ float Sp[32*33];
    __shared__ float kp[32];
    __shared__ float Am[CHUNK*65];
    __shared__ float den[CHUNK];

    int tid  = threadIdx.x;
    int lane = tid & 31;
    int w    = tid >> 5;
    size_t rowbase = ((size_t)(b*GDIM + c*CHUNK))*DDIM + hh*HEADDIM;

    for (int t = w; t < CHUNK; t += 8) {
        size_t g = rowbase + (size_t)t*DDIM + lane;
        Qs[t*33 + lane] = Q[g];
        Ks[t*33 + lane] = K[g];
        Vs[t*33 + lane] = V[g];
    }
    const float* st = state + (size_t)blk * STATE_STRIDE;
    for (int e = tid; e < 1024; e += 256)
        Sp[(e & 31)*33 + (e >> 5)] = st[e];
    if (tid < 32) kp[tid] = st[1024 + tid];
    __syncthreads();

    {
        int tt = (tid >> 4) << 2;
        int ss = (tid & 15) << 2;
        float acc[4][4];
        #pragma unroll
        for (int i = 0; i < 4; i++)
            #pragma unroll
            for (int j = 0; j < 4; j++) acc[i][j] = 0.f;
        for (int f = 0; f < 32; f++) {
            float qv[4], kv[4];
            #pragma unroll
            for (int i = 0; i < 4; i++) qv[i] = Qs[(tt+i)*33 + f];
            #pragma unroll
            for (int j = 0; j < 4; j++) kv[j] = Ks[(ss+j)*33 + f];
            #pragma unroll
            for (int i = 0; i < 4; i++)
                #pragma unroll
                for (int j = 0; j < 4; j++)
                    acc[i][j] = fmaf(qv[i], kv[j], acc[i][j]);
        }
        #pragma unroll
        for (int i = 0; i < 4; i++)
            #pragma unroll
            for (int j = 0; j < 4; j++)
                Am[(tt+i)*65 + ss+j] = (ss+j <= tt+i) ? acc[i][j] : 0.f;
    }
    __syncthreads();

    if (tid < CHUNK) {
        float s = 0.f;
        for (int ss = 0; ss <= tid; ss++) s += Am[tid*65 + ss];
        for (int f = 0; f < 32; f++) s += Qs[tid*33 + f] * kp[f];
        den[tid] = s + 1e-16f;
    }
    __syncthreads();

    int d = lane;
    float acc[8];
    #pragma unroll
    for (int i = 0; i < 8; i++) acc[i] = 0.f;
    for (int f = 0; f < 32; f++) {
        float sp = Sp[f*33 + d];
        #pragma unroll
        for (int i = 0; i < 8; i++)
            acc[i] = fmaf(Qs[(w*8+i)*33 + f], sp, acc[i]);
    }
    for (int s = 0; s < CHUNK; s++) {
        float vv = Vs[s*33 + d];
        #pragma unroll
        for (int i = 0; i < 8; i++)
            acc[i] = fmaf(Am[(w*8+i)*65 + s], vv, acc[i]);
    }
    #pragma unroll
    for (int i = 0; i < 8; i++) {
        int t = w*8 + i;
        H[rowbase + (size_t)t*DDIM + d] += acc[i] / den[t];
    }
}

// ---------------------------------------------------------------------------
// Output projection
// ---------------------------------------------------------------------------
__global__ void outproj_kernel(const float* __restrict__ H,
                               const float* __restrict__ Wout,
                               const float* __restrict__ bout,
                               float* __restrict__ out) {
    int row  = blockIdx.x * 8 + (threadIdx.x >> 5);
    int lane = threadIdx.x & 31;
    float s = 0.f;
    #pragma unroll
    for (int i = 0; i < 8; i++) {
        int c = lane + i*32;
        s += H[(size_t)row*DDIM + c] * Wout[c];
    }
    #pragma unroll
    for (int o = 16; o; o >>= 1) s += __shfl_xor_sync(0xffffffffu, s, o);
    if (lane == 0) out[row] = s + bout[0];
}

// ---------------------------------------------------------------------------
extern "C" void kernel_launch(void* const* d_in, const int* in_sizes, int n_in,
                              void* d_out, int out_size) {
    const float* x        = (const float*)d_in[0];
    const float* gene_emb = (const float*)d_in[1];
    const float* inv_freq = (const float*)d_in[2];
    const float* Wq   = (const float*)d_in[3];
    const float* bq   = (const float*)d_in[4];
    const float* Wk   = (const float*)d_in[5];
    const float* bk   = (const float*)d_in[6];
    const float* Wv   = (const float*)d_in[7];
    const float* bv   = (const float*)d_in[8];
    const float* ln1g = (const float*)d_in[9];
    const float* ln1b = (const float*)d_in[10];
    const float* ln2g = (const float*)d_in[11];
    const float* ln2b = (const float*)d_in[12];
    const float* WU   = (const float*)d_in[13];
    const float* bU   = (const float*)d_in[14];
    const float* WV   = (const float*)d_in[15];
    const float* bV   = (const float*)d_in[16];
    const float* Wout = (const float*)d_in[17];
    const float* bout = (const float*)d_in[18];
    float* out = (float*)d_out;

    float *h, *q, *k, *v, *stt;
    cudaGetSymbolAddress((void**)&h,   g_h);
    cudaGetSymbolAddress((void**)&q,   g_q);
    cudaGetSymbolAddress((void**)&k,   g_k);
    cudaGetSymbolAddress((void**)&v,   g_v);
    cudaGetSymbolAddress((void**)&stt, g_state);

    __nv_bfloat16 *hnhi, *hnlo, *midhi, *midlo;
    __nv_bfloat16 *wqkvh, *wqkvl, *wuh, *wul, *wvh2, *wvl2;
    cudaGetSymbolAddress((void**)&hnhi,  g_hnhi);
    cudaGetSymbolAddress((void**)&hnlo,  g_hnlo);
    cudaGetSymbolAddress((void**)&midhi, g_midhi);
    cudaGetSymbolAddress((void**)&midlo, g_midlo);
    cudaGetSymbolAddress((void**)&wqkvh, g_wqkvh);
    cudaGetSymbolAddress((void**)&wqkvl, g_wqkvl);
    cudaGetSymbolAddress((void**)&wuh,   g_wuh);
    cudaGetSymbolAddress((void**)&wul,   g_wul);
    cudaGetSymbolAddress((void**)&wvh2,  g_wvh2);
    cudaGetSymbolAddress((void**)&wvl2,  g_wvl2);

    cudaFuncSetAttribute(tc_gemm2<1>, cudaFuncAttributeMaxDynamicSharedMemorySize, S_SMEM);
    cudaFuncSetAttribute(tc_gemm2<2>, cudaFuncAttributeMaxDynamicSharedMemorySize, S_SMEM);
    cudaFuncSetAttribute(tc_gemm2<3>, cudaFuncAttributeMaxDynamicSharedMemorySize, S_SMEM);

    // Weight conversion: 5 batched launches (z = layer)
    wconv_kernel<<<dim3(8, 8, LAYERS),  256>>>(Wq, wqkvh, wqkvl, DDIM, DDIM,   0, 768);
    wconv_kernel<<<dim3(8, 8, LAYERS),  256>>>(Wk, wqkvh, wqkvl, DDIM, DDIM, 256, 768);
    wconv_kernel<<<dim3(8, 8, LAYERS),  256>>>(Wv, wqkvh, wqkvl, DDIM, DDIM, 512, 768);
    wconv_kernel<<<dim3(32, 8, LAYERS), 256>>>(WU, wuh,  wul,  DDIM, FFND, 0, FFND);
    wconv_kernel<<<dim3(8, 32, LAYERS), 256>>>(WV, wvh2, wvl2, FFND, DDIM, 0, DDIM);

    embed_kernel<<<ROWS, 128>>>(x, gene_emb, inv_freq, h);

    dim3 gQKV(ROWS/128, 768/128);    // (256, 6)
    dim3 gUP (ROWS/128, FFND/128);   // (256, 8)
    dim3 gDN (ROWS/128, DDIM/128);   // (256, 2)

    for (int l = 0; l < LAYERS; l++) {
        ln_bf16_kernel<<<ROWS, 256>>>(h, ln1g + l*DDIM, ln1b + l*DDIM, hnhi, hnlo);
        tc_gemm2<1><<<gQKV, 256, S_SMEM>>>(hnhi, hnlo,
            wqkvh + (size_t)l*768*DDIM, wqkvl + (size_t)l*768*DDIM,
            bq + l*DDIM, bk + l*DDIM, bv + l*DDIM, nullptr,
            q, k, v, nullptr, nullptr, DDIM, DDIM);

        attn_state_kernel <<<BH*NCHUNK, 1024>>>(k, v, stt);
        attn_prefix_kernel<<<BH, 1024>>>(stt);
        attn_out_kernel   <<<BH*NCHUNK, 256>>>(q, k, v, stt, h);

        ln_bf16_kernel<<<ROWS, 256>>>(h, ln2g + l*DDIM, ln2b + l*DDIM, hnhi, hnlo);
        tc_gemm2<2><<<gUP, 256, S_SMEM>>>(hnhi, hnlo,
            wuh + (size_t)l*DDIM*FFND, wul + (size_t)l*DDIM*FFND,
            bU + l*FFND, nullptr, nullptr, nullptr,
            nullptr, nullptr, nullptr, midhi, midlo, FFND, DDIM);
        tc_gemm2<3><<<gDN, 256, S_SMEM>>>(midhi, midlo,
            wvh2 + (size_t)l*FFND*DDIM, wvl2 + (size_t)l*FFND*DDIM,
            bV + l*DDIM, nullptr, nullptr, h,
            h, nullptr, nullptr, nullptr, nullptr, DDIM, FFND);
    }

    outproj_kernel<<<ROWS/8, 256>>>(h, Wout, bout, out);
}